// round 6
// baseline (speedup 1.0000x reference)
#include <cuda_runtime.h>
#include <cuda_bf16.h>
#include <cstddef>

// Problem constants (from reference)
#define NFRAMES 8
#define NLOC    4096
#define NALL    8192
#define NNEI    256
#define NTYPES  4
#define NSPLINE 1024

static constexpr int CTAS_PER_FRAME = 16;   // 16*8 = 128 CTAs, one wave on 148 SMs
static constexpr int THREADS        = 1024; // 32 warps/CTA
static constexpr int WARPS          = THREADS / 32;
static constexpr int ATOMS_PER_CTA  = NLOC / CTAS_PER_FRAME; // 256 -> 8 atoms per warp

// Shared: one float4 per extended atom of this frame: (x, y, z, bitcast(type))
// 8192 * 16 B = 131072 B dynamic smem -> 1 CTA / SM.

__global__ __launch_bounds__(THREADS, 1)
void pairtab_energy_kernel(const float*  __restrict__ coord,   // (NFRAMES, NALL, 3)
                           const int*    __restrict__ atype,   // (NFRAMES, NALL)
                           const int*    __restrict__ nlist,   // (NFRAMES, NLOC, NNEI)
                           const float4* __restrict__ tab,     // (NTYPES, NTYPES, NSPLINE) float4
                           float*        __restrict__ out)     // (NFRAMES, NLOC)
{
    extern __shared__ float4 s_pack[]; // [NALL]

    const int f   = blockIdx.y;
    const int tid = threadIdx.x;

    // ---- Stage coords + types of this frame into smem (coalesced) ----
    {
        const float* cf = coord + (size_t)f * NALL * 3;
        const int*   af = atype + (size_t)f * NALL;
        #pragma unroll
        for (int a = tid; a < NALL; a += THREADS) {
            float x = cf[a * 3 + 0];
            float y = cf[a * 3 + 1];
            float z = cf[a * 3 + 2];
            int   t = af[a];
            s_pack[a] = make_float4(x, y, z, __int_as_float(t));
        }
    }
    __syncthreads();

    const int lane  = tid & 31;
    const int wid   = tid >> 5;
    const int atom0 = blockIdx.x * ATOMS_PER_CTA;

    // One warp per atom; each lane handles 8 neighbors (2x int4 nlist loads).
    for (int aa = wid; aa < ATOMS_PER_CTA; aa += WARPS) {
        const int atom = atom0 + aa;
        const float4 pi = s_pack[atom];
        const int ti_base = __float_as_int(pi.w) * NTYPES; // i_type * NTYPES

        const int4* nl = reinterpret_cast<const int4*>(
            nlist + ((size_t)f * NLOC + atom) * NNEI);

        float acc = 0.0f;

        #pragma unroll
        for (int c = 0; c < NNEI / (4 * 32); ++c) {  // 2 iterations
            const int4 n4 = nl[c * 32 + lane];
            const int js[4] = { n4.x, n4.y, n4.z, n4.w };

            #pragma unroll
            for (int k = 0; k < 4; ++k) {
                const int j = js[k];
                if (j < 0) continue;                  // invalid neighbor -> 0

                const float4 pj = s_pack[j];
                const float dx = __fadd_rn(pi.x, -pj.x);
                const float dy = __fadd_rn(pi.y, -pj.y);
                const float dz = __fadd_rn(pi.z, -pj.z);
                // Tree-reduce association (pad to 4, stride-2-first pairwise):
                //   r2 = (dx*dx + dz*dz) + (dy*dy + 0)
                // i.e. y-last, fully UNcontracted (no FMA).
                const float sxz = __fadd_rn(__fmul_rn(dx, dx), __fmul_rn(dz, dz));
                const float r2  = __fadd_rn(sxz, __fmul_rn(dy, dy));
                const float rr = __fsqrt_rn(r2);
                // XLA rewrites (rr - 0)/0.02 into rr * (1/0.02f); 1/0.02f rounds
                // to exactly 50.0f. Must multiply, not divide, to match bins.
                const float uu = __fmul_rn(rr, 50.0f);
                const int  idx = (int)uu;              // trunc toward zero, uu >= 0

                if (idx < NSPLINE) {
                    const float frac = __fadd_rn(uu, -(float)idx);
                    const int   tj   = __float_as_int(pj.w);
                    const float4 cc  = __ldg(&tab[(size_t)(ti_base + tj) * NSPLINE + idx]);
                    // Horner: ((c3*f + c2)*f + c1)*f + c0
                    float e = fmaf(cc.w, frac, cc.z);
                    e = fmaf(e, frac, cc.y);
                    e = fmaf(e, frac, cc.x);
                    acc += e;
                }
                // idx >= NSPLINE -> coef zeroed -> energy 0 (skip)
            }
        }

        // Warp reduction
        #pragma unroll
        for (int o = 16; o > 0; o >>= 1)
            acc += __shfl_xor_sync(0xffffffffu, acc, o);

        if (lane == 0)
            out[(size_t)f * NLOC + atom] = 0.5f * acc;
    }
}

extern "C" void kernel_launch(void* const* d_in, const int* in_sizes, int n_in,
                              void* d_out, int out_size)
{
    const float*  coord = (const float*)  d_in[0]; // (8, 8192, 3) f32
    const int*    atype = (const int*)    d_in[1]; // (8, 8192) i32
    const int*    nlist = (const int*)    d_in[2]; // (8, 4096, 256) i32
    const float4* tab   = (const float4*) d_in[3]; // (4, 4, 1024, 4) f32 -> float4
    float*        out   = (float*)        d_out;   // (8, 4096) f32

    const int smem_bytes = NALL * (int)sizeof(float4); // 131072
    cudaFuncSetAttribute(pairtab_energy_kernel,
                         cudaFuncAttributeMaxDynamicSharedMemorySize, smem_bytes);

    dim3 grid(CTAS_PER_FRAME, NFRAMES);
    pairtab_energy_kernel<<<grid, THREADS, smem_bytes>>>(coord, atype, nlist, tab, out);
}

// round 7
// speedup vs baseline: 1.0452x; 1.0452x over previous
#include <cuda_runtime.h>
#include <cuda_bf16.h>
#include <cstddef>

// Problem constants (from reference)
#define NFRAMES 8
#define NLOC    4096
#define NALL    8192
#define NNEI    256
#define NTYPES  4
#define NSPLINE 1024

static constexpr int THREADS        = 1024; // 32 warps/CTA
static constexpr int WARPS          = THREADS / 32;
static constexpr int CHUNKS         = 4;    // chunks per (frame, type) bin
static constexpr int CTAS_X         = NTYPES * CHUNKS; // 16 -> grid (16, 8) = 128 CTAs

// Scratch for type binning (device globals: allocation-free)
__device__ int g_counts[NFRAMES * NTYPES];
__device__ int g_lists [NFRAMES * NTYPES * NLOC];

// ---------------- Pre-pass: bin local atoms by their own type ----------------
__global__ __launch_bounds__(THREADS, 1)
void bin_by_type_kernel(const int* __restrict__ atype) // (NFRAMES, NALL)
{
    const int f   = blockIdx.x;
    const int tid = threadIdx.x;
    __shared__ int s_hist[NTYPES];
    __shared__ int s_off [NTYPES];

    if (tid < NTYPES) { s_hist[tid] = 0; }
    __syncthreads();

    const int* af = atype + (size_t)f * NALL; // local atoms are the first NLOC
    for (int a = tid; a < NLOC; a += THREADS)
        atomicAdd(&s_hist[af[a]], 1);
    __syncthreads();

    if (tid < NTYPES) {
        g_counts[f * NTYPES + tid] = s_hist[tid];
        s_off[tid] = 0;
    }
    __syncthreads();

    for (int a = tid; a < NLOC; a += THREADS) {
        const int t    = af[a];
        const int slot = atomicAdd(&s_off[t], 1);
        g_lists[(f * NTYPES + t) * NLOC + slot] = a;
    }
}

// ---------------- Main kernel ----------------
// Dynamic smem: s_pack float4[NALL] (128KB) + s_tab float4[NTYPES*NSPLINE] (64KB)
__global__ __launch_bounds__(THREADS, 1)
void pairtab_energy_kernel(const float*  __restrict__ coord,   // (NFRAMES, NALL, 3)
                           const int*    __restrict__ atype,   // (NFRAMES, NALL)
                           const int*    __restrict__ nlist,   // (NFRAMES, NLOC, NNEI)
                           const float4* __restrict__ tab,     // (NTYPES,NTYPES,NSPLINE) float4
                           float*        __restrict__ out)     // (NFRAMES, NLOC)
{
    extern __shared__ float4 s_mem[];
    float4* s_pack = s_mem;          // [NALL]
    float4* s_tab  = s_mem + NALL;   // [NTYPES * NSPLINE]

    const int f     = blockIdx.y;
    const int t     = blockIdx.x >> 2;   // i_type this CTA serves
    const int chunk = blockIdx.x & 3;
    const int tid   = threadIdx.x;

    // ---- Stage coords + types of this frame (coalesced) ----
    {
        const float* cf = coord + (size_t)f * NALL * 3;
        const int*   af = atype + (size_t)f * NALL;
        for (int a = tid; a < NALL; a += THREADS) {
            float x = cf[a * 3 + 0];
            float y = cf[a * 3 + 1];
            float z = cf[a * 3 + 2];
            int   ty = af[a];
            s_pack[a] = make_float4(x, y, z, __int_as_float(ty));
        }
    }
    // ---- Stage tab[t] : NTYPES*NSPLINE float4 = 64KB (coalesced) ----
    {
        const float4* tf = tab + (size_t)t * NTYPES * NSPLINE;
        for (int i = tid; i < NTYPES * NSPLINE; i += THREADS)
            s_tab[i] = tf[i];
    }
    __syncthreads();

    const int lane = tid & 31;
    const int wid  = tid >> 5;

    const int  cnt   = g_counts[f * NTYPES + t];
    const int  m     = (cnt + CHUNKS - 1) / CHUNKS;
    const int  start = chunk * m;
    const int  end   = min(start + m, cnt);
    const int* list  = g_lists + (f * NTYPES + t) * NLOC;

    for (int k = start + wid; k < end; k += WARPS) {
        const int atom = list[k];
        const float4 pi = s_pack[atom];

        const int4* nl = reinterpret_cast<const int4*>(
            nlist + ((size_t)f * NLOC + atom) * NNEI);

        float acc = 0.0f;

        #pragma unroll
        for (int c = 0; c < NNEI / (4 * 32); ++c) {  // 2 iterations
            const int4 n4 = nl[c * 32 + lane];
            const int js[4] = { n4.x, n4.y, n4.z, n4.w };

            #pragma unroll
            for (int kk = 0; kk < 4; ++kk) {
                const int j      = js[kk];
                const bool jval  = (j >= 0);
                const int  jj    = jval ? j : 0;

                const float4 pj = s_pack[jj];
                const float dx = __fadd_rn(pi.x, -pj.x);
                const float dy = __fadd_rn(pi.y, -pj.y);
                const float dz = __fadd_rn(pi.z, -pj.z);
                // Reference association (verified R5): (dx^2 + dz^2) + dy^2,
                // fully uncontracted.
                const float sxz = __fadd_rn(__fmul_rn(dx, dx), __fmul_rn(dz, dz));
                const float r2  = __fadd_rn(sxz, __fmul_rn(dy, dy));
                const float rr  = __fsqrt_rn(r2);
                // Reference computes uu = rr * (1/0.02f) = rr * 50.0f exactly.
                const float uu  = __fmul_rn(rr, 50.0f);
                const int   idx = (int)uu;          // trunc, uu >= 0

                const bool  v    = jval && (idx < NSPLINE);
                const int   ci   = min(idx, NSPLINE - 1);
                const float frac = __fadd_rn(uu, -(float)idx);
                const int   tj   = __float_as_int(pj.w);

                const float4 cc = s_tab[tj * NSPLINE + ci];
                float e = fmaf(cc.w, frac, cc.z);
                e = fmaf(e, frac, cc.y);
                e = fmaf(e, frac, cc.x);
                acc += v ? e : 0.0f;
            }
        }

        // Warp reduction
        #pragma unroll
        for (int o = 16; o > 0; o >>= 1)
            acc += __shfl_xor_sync(0xffffffffu, acc, o);

        if (lane == 0)
            out[(size_t)f * NLOC + atom] = 0.5f * acc;
    }
}

extern "C" void kernel_launch(void* const* d_in, const int* in_sizes, int n_in,
                              void* d_out, int out_size)
{
    const float*  coord = (const float*)  d_in[0]; // (8, 8192, 3) f32
    const int*    atype = (const int*)    d_in[1]; // (8, 8192) i32
    const int*    nlist = (const int*)    d_in[2]; // (8, 4096, 256) i32
    const float4* tab   = (const float4*) d_in[3]; // (4, 4, 1024, 4) f32 -> float4
    float*        out   = (float*)        d_out;   // (8, 4096) f32

    const int smem_bytes = (NALL + NTYPES * NSPLINE) * (int)sizeof(float4); // 196608
    static bool attr_set = false;
    if (!attr_set) {
        cudaFuncSetAttribute(pairtab_energy_kernel,
                             cudaFuncAttributeMaxDynamicSharedMemorySize, smem_bytes);
        attr_set = true;
    }

    bin_by_type_kernel<<<NFRAMES, THREADS>>>(atype);

    dim3 grid(CTAS_X, NFRAMES);
    pairtab_energy_kernel<<<grid, THREADS, smem_bytes>>>(coord, atype, nlist, tab, out);
}

// round 8
// speedup vs baseline: 1.0519x; 1.0065x over previous
#include <cuda_runtime.h>
#include <cuda_bf16.h>
#include <cstddef>

// Problem constants (from reference)
#define NFRAMES 8
#define NLOC    4096
#define NALL    8192
#define NNEI    256
#define NTYPES  4
#define NSPLINE 1024

static constexpr int THREADS        = 1024; // 32 warps/CTA
static constexpr int WARPS          = THREADS / 32;
static constexpr int CHUNKS         = 4;    // chunks per (frame, type) bin
static constexpr int CTAS_X         = NTYPES * CHUNKS; // 16 -> grid (16, 8) = 128 CTAs

// Scratch for type binning (device globals: allocation-free)
__device__ int g_counts[NFRAMES * NTYPES];
__device__ int g_lists [NFRAMES * NTYPES * NLOC];

// ---------------- Pre-pass: bin local atoms by their own type ----------------
__global__ __launch_bounds__(THREADS, 1)
void bin_by_type_kernel(const int* __restrict__ atype) // (NFRAMES, NALL)
{
    const int f   = blockIdx.x;
    const int tid = threadIdx.x;
    __shared__ int s_hist[NTYPES];
    __shared__ int s_off [NTYPES];

    if (tid < NTYPES) { s_hist[tid] = 0; }
    __syncthreads();

    const int* af = atype + (size_t)f * NALL; // local atoms are the first NLOC
    for (int a = tid; a < NLOC; a += THREADS)
        atomicAdd(&s_hist[af[a]], 1);
    __syncthreads();

    if (tid < NTYPES) {
        g_counts[f * NTYPES + tid] = s_hist[tid];
        s_off[tid] = 0;
    }
    __syncthreads();

    for (int a = tid; a < NLOC; a += THREADS) {
        const int t    = af[a];
        const int slot = atomicAdd(&s_off[t], 1);
        g_lists[(f * NTYPES + t) * NLOC + slot] = a;
    }
}

// ---------------- Main kernel ----------------
// Dynamic smem: s_pack float4[NALL] (128KB) + s_tab float4[NTYPES*NSPLINE] (64KB)
__global__ __launch_bounds__(THREADS, 1)
void pairtab_energy_kernel(const float*  __restrict__ coord,   // (NFRAMES, NALL, 3)
                           const int*    __restrict__ atype,   // (NFRAMES, NALL)
                           const int*    __restrict__ nlist,   // (NFRAMES, NLOC, NNEI)
                           const float4* __restrict__ tab,     // (NTYPES,NTYPES,NSPLINE) float4
                           float*        __restrict__ out)     // (NFRAMES, NLOC)
{
    extern __shared__ float4 s_mem[];
    float4* s_pack = s_mem;          // [NALL]
    float4* s_tab  = s_mem + NALL;   // [NTYPES * NSPLINE]

    const int f     = blockIdx.y;
    const int t     = blockIdx.x >> 2;   // i_type this CTA serves
    const int chunk = blockIdx.x & 3;
    const int tid   = threadIdx.x;

    // ---- Stage coords + types of this frame (coalesced) ----
    {
        const float* cf = coord + (size_t)f * NALL * 3;
        const int*   af = atype + (size_t)f * NALL;
        for (int a = tid; a < NALL; a += THREADS) {
            float x = cf[a * 3 + 0];
            float y = cf[a * 3 + 1];
            float z = cf[a * 3 + 2];
            int   ty = af[a];
            s_pack[a] = make_float4(x, y, z, __int_as_float(ty));
        }
    }
    // ---- Stage tab[t] : NTYPES*NSPLINE float4 = 64KB (coalesced) ----
    {
        const float4* tf = tab + (size_t)t * NTYPES * NSPLINE;
        for (int i = tid; i < NTYPES * NSPLINE; i += THREADS)
            s_tab[i] = tf[i];
    }
    __syncthreads();

    const int lane = tid & 31;
    const int wid  = tid >> 5;

    const int  cnt   = g_counts[f * NTYPES + t];
    const int  m     = (cnt + CHUNKS - 1) / CHUNKS;
    const int  start = chunk * m;
    const int  end   = min(start + m, cnt);
    const int* list  = g_lists + (f * NTYPES + t) * NLOC;

    for (int k = start + wid; k < end; k += WARPS) {
        const int atom = list[k];
        const float4 pi = s_pack[atom];

        const int4* nl = reinterpret_cast<const int4*>(
            nlist + ((size_t)f * NLOC + atom) * NNEI);

        float acc = 0.0f;

        #pragma unroll
        for (int c = 0; c < NNEI / (4 * 32); ++c) {  // 2 iterations
            const int4 n4 = nl[c * 32 + lane];
            const int js[4] = { n4.x, n4.y, n4.z, n4.w };

            #pragma unroll
            for (int kk = 0; kk < 4; ++kk) {
                const int j      = js[kk];
                const bool jval  = (j >= 0);
                const int  jj    = jval ? j : 0;

                const float4 pj = s_pack[jj];
                const float dx = __fadd_rn(pi.x, -pj.x);
                const float dy = __fadd_rn(pi.y, -pj.y);
                const float dz = __fadd_rn(pi.z, -pj.z);
                // Reference association (verified R5): (dx^2 + dz^2) + dy^2,
                // fully uncontracted.
                const float sxz = __fadd_rn(__fmul_rn(dx, dx), __fmul_rn(dz, dz));
                const float r2  = __fadd_rn(sxz, __fmul_rn(dy, dy));
                const float rr  = __fsqrt_rn(r2);
                // Reference computes uu = rr * (1/0.02f) = rr * 50.0f exactly.
                const float uu  = __fmul_rn(rr, 50.0f);
                const int   idx = (int)uu;          // trunc, uu >= 0

                const bool  v    = jval && (idx < NSPLINE);
                const int   ci   = min(idx, NSPLINE - 1);
                const float frac = __fadd_rn(uu, -(float)idx);
                const int   tj   = __float_as_int(pj.w);

                const float4 cc = s_tab[tj * NSPLINE + ci];
                float e = fmaf(cc.w, frac, cc.z);
                e = fmaf(e, frac, cc.y);
                e = fmaf(e, frac, cc.x);
                acc += v ? e : 0.0f;
            }
        }

        // Warp reduction
        #pragma unroll
        for (int o = 16; o > 0; o >>= 1)
            acc += __shfl_xor_sync(0xffffffffu, acc, o);

        if (lane == 0)
            out[(size_t)f * NLOC + atom] = 0.5f * acc;
    }
}

extern "C" void kernel_launch(void* const* d_in, const int* in_sizes, int n_in,
                              void* d_out, int out_size)
{
    const float*  coord = (const float*)  d_in[0]; // (8, 8192, 3) f32
    const int*    atype = (const int*)    d_in[1]; // (8, 8192) i32
    const int*    nlist = (const int*)    d_in[2]; // (8, 4096, 256) i32
    const float4* tab   = (const float4*) d_in[3]; // (4, 4, 1024, 4) f32 -> float4
    float*        out   = (float*)        d_out;   // (8, 4096) f32

    const int smem_bytes = (NALL + NTYPES * NSPLINE) * (int)sizeof(float4); // 196608
    static bool attr_set = false;
    if (!attr_set) {
        cudaFuncSetAttribute(pairtab_energy_kernel,
                             cudaFuncAttributeMaxDynamicSharedMemorySize, smem_bytes);
        attr_set = true;
    }

    bin_by_type_kernel<<<NFRAMES, THREADS>>>(atype);

    dim3 grid(CTAS_X, NFRAMES);
    pairtab_energy_kernel<<<grid, THREADS, smem_bytes>>>(coord, atype, nlist, tab, out);
}

// round 9
// speedup vs baseline: 1.0528x; 1.0008x over previous
#include <cuda_runtime.h>
#include <cuda_bf16.h>
#include <cstddef>

// Problem constants (from reference)
#define NFRAMES 8
#define NLOC    4096
#define NALL    8192
#define NNEI    256
#define NTYPES  4
#define NSPLINE 1024

static constexpr int THREADS        = 1024; // 32 warps/CTA
static constexpr int WARPS          = THREADS / 32;
static constexpr int CHUNKS         = 4;    // chunks per (frame, type) bin
static constexpr int CTAS_X         = NTYPES * CHUNKS; // 16 -> grid (16, 8) = 128 CTAs

// Scratch for type binning (device globals: allocation-free)
__device__ int g_counts[NFRAMES * NTYPES];
__device__ int g_lists [NFRAMES * NTYPES * NLOC];

// ---------------- Pre-pass: bin local atoms by their own type ----------------
__global__ __launch_bounds__(THREADS, 1)
void bin_by_type_kernel(const int* __restrict__ atype) // (NFRAMES, NALL)
{
    const int f   = blockIdx.x;
    const int tid = threadIdx.x;
    __shared__ int s_hist[NTYPES];
    __shared__ int s_off [NTYPES];

    if (tid < NTYPES) { s_hist[tid] = 0; }
    __syncthreads();

    const int* af = atype + (size_t)f * NALL; // local atoms are the first NLOC
    for (int a = tid; a < NLOC; a += THREADS)
        atomicAdd(&s_hist[af[a]], 1);
    __syncthreads();

    if (tid < NTYPES) {
        g_counts[f * NTYPES + tid] = s_hist[tid];
        s_off[tid] = 0;
    }
    __syncthreads();

    for (int a = tid; a < NLOC; a += THREADS) {
        const int t    = af[a];
        const int slot = atomicAdd(&s_off[t], 1);
        g_lists[(f * NTYPES + t) * NLOC + slot] = a;
    }
}

// ---------------- Main kernel ----------------
// Dynamic smem: s_pack float4[NALL] (128KB) + s_tab float4[NTYPES*NSPLINE] (64KB)
__global__ __launch_bounds__(THREADS, 1)
void pairtab_energy_kernel(const float*  __restrict__ coord,   // (NFRAMES, NALL, 3)
                           const int*    __restrict__ atype,   // (NFRAMES, NALL)
                           const int*    __restrict__ nlist,   // (NFRAMES, NLOC, NNEI)
                           const float4* __restrict__ tab,     // (NTYPES,NTYPES,NSPLINE) float4
                           float*        __restrict__ out)     // (NFRAMES, NLOC)
{
    extern __shared__ float4 s_mem[];
    float4* s_pack = s_mem;          // [NALL]
    float4* s_tab  = s_mem + NALL;   // [NTYPES * NSPLINE]

    const int f     = blockIdx.y;
    const int t     = blockIdx.x >> 2;   // i_type this CTA serves
    const int chunk = blockIdx.x & 3;
    const int tid   = threadIdx.x;

    // ---- Stage coords + types of this frame (coalesced) ----
    {
        const float* cf = coord + (size_t)f * NALL * 3;
        const int*   af = atype + (size_t)f * NALL;
        for (int a = tid; a < NALL; a += THREADS) {
            float x = cf[a * 3 + 0];
            float y = cf[a * 3 + 1];
            float z = cf[a * 3 + 2];
            int   ty = af[a];
            s_pack[a] = make_float4(x, y, z, __int_as_float(ty));
        }
    }
    // ---- Stage tab[t] : NTYPES*NSPLINE float4 = 64KB (coalesced) ----
    {
        const float4* tf = tab + (size_t)t * NTYPES * NSPLINE;
        for (int i = tid; i < NTYPES * NSPLINE; i += THREADS)
            s_tab[i] = tf[i];
    }
    __syncthreads();

    const int lane = tid & 31;
    const int wid  = tid >> 5;

    const int  cnt   = g_counts[f * NTYPES + t];
    const int  m     = (cnt + CHUNKS - 1) / CHUNKS;
    const int  start = chunk * m;
    const int  end   = min(start + m, cnt);
    const int* list  = g_lists + (f * NTYPES + t) * NLOC;

    for (int k = start + wid; k < end; k += WARPS) {
        const int atom = list[k];
        const float4 pi = s_pack[atom];

        const int4* nl = reinterpret_cast<const int4*>(
            nlist + ((size_t)f * NLOC + atom) * NNEI);

        float acc = 0.0f;

        #pragma unroll
        for (int c = 0; c < NNEI / (4 * 32); ++c) {  // 2 iterations
            const int4 n4 = nl[c * 32 + lane];
            const int js[4] = { n4.x, n4.y, n4.z, n4.w };

            #pragma unroll
            for (int kk = 0; kk < 4; ++kk) {
                const int j      = js[kk];
                const bool jval  = (j >= 0);
                const int  jj    = jval ? j : 0;

                const float4 pj = s_pack[jj];
                const float dx = __fadd_rn(pi.x, -pj.x);
                const float dy = __fadd_rn(pi.y, -pj.y);
                const float dz = __fadd_rn(pi.z, -pj.z);
                // Reference association (verified R5): (dx^2 + dz^2) + dy^2,
                // fully uncontracted.
                const float sxz = __fadd_rn(__fmul_rn(dx, dx), __fmul_rn(dz, dz));
                const float r2  = __fadd_rn(sxz, __fmul_rn(dy, dy));
                const float rr  = __fsqrt_rn(r2);
                // Reference computes uu = rr * (1/0.02f) = rr * 50.0f exactly.
                const float uu  = __fmul_rn(rr, 50.0f);
                const int   idx = (int)uu;          // trunc, uu >= 0

                const bool  v    = jval && (idx < NSPLINE);
                const int   ci   = min(idx, NSPLINE - 1);
                const float frac = __fadd_rn(uu, -(float)idx);
                const int   tj   = __float_as_int(pj.w);

                const float4 cc = s_tab[tj * NSPLINE + ci];
                float e = fmaf(cc.w, frac, cc.z);
                e = fmaf(e, frac, cc.y);
                e = fmaf(e, frac, cc.x);
                acc += v ? e : 0.0f;
            }
        }

        // Warp reduction
        #pragma unroll
        for (int o = 16; o > 0; o >>= 1)
            acc += __shfl_xor_sync(0xffffffffu, acc, o);

        if (lane == 0)
            out[(size_t)f * NLOC + atom] = 0.5f * acc;
    }
}

extern "C" void kernel_launch(void* const* d_in, const int* in_sizes, int n_in,
                              void* d_out, int out_size)
{
    const float*  coord = (const float*)  d_in[0]; // (8, 8192, 3) f32
    const int*    atype = (const int*)    d_in[1]; // (8, 8192) i32
    const int*    nlist = (const int*)    d_in[2]; // (8, 4096, 256) i32
    const float4* tab   = (const float4*) d_in[3]; // (4, 4, 1024, 4) f32 -> float4
    float*        out   = (float*)        d_out;   // (8, 4096) f32

    const int smem_bytes = (NALL + NTYPES * NSPLINE) * (int)sizeof(float4); // 196608
    static bool attr_set = false;
    if (!attr_set) {
        cudaFuncSetAttribute(pairtab_energy_kernel,
                             cudaFuncAttributeMaxDynamicSharedMemorySize, smem_bytes);
        attr_set = true;
    }

    bin_by_type_kernel<<<NFRAMES, THREADS>>>(atype);

    dim3 grid(CTAS_X, NFRAMES);
    pairtab_energy_kernel<<<grid, THREADS, smem_bytes>>>(coord, atype, nlist, tab, out);
}